// round 4
// baseline (speedup 1.0000x reference)
#include <cuda_runtime.h>
#include <math.h>

#define NUMN  65536
#define NG    64
#define NPG   1024
#define DIMC  128
#define NEDGE 2097152
#define PITCH 132
#define SMEM_BYTES (2 * 128 * PITCH * 4)
#define INFV  3.402823466e38f

// ---------------- scratch (device globals; no allocation allowed) ----------------
__device__ float g_xn  [NUMN * DIMC];   // normalized x
__device__ float g_h1  [NUMN * DIMC];   // dinv-scaled h_feat
__device__ float g_h2  [NUMN * DIMC];   // dinv-scaled h_stru
__device__ float g_acc1[NUMN * DIMC];   // aggregation accumulators (init = self term)
__device__ float g_acc2[NUMN * DIMC];
__device__ float g_feat[NUMN * DIMC];   // post-LN branch outputs
__device__ float g_stru[NUMN * DIMC];
__device__ float g_gate[NUMN * DIMC];   // sigmoid gate
__device__ int   g_fdst[NUMN * 4];      // k-farthest dst indices (global node ids)
__device__ int   g_deg1[NUMN];
__device__ int   g_deg2[NUMN];
__device__ float g_dinv1[NUMN];
__device__ float g_dinv2[NUMN];

// ---------------- helpers ----------------
__device__ __forceinline__ float warp_sum(float v) {
    #pragma unroll
    for (int o = 16; o; o >>= 1) v += __shfl_xor_sync(0xffffffffu, v, o);
    return v;
}

__device__ __forceinline__ void red4(float* p, float4 v) {
    asm volatile("red.global.add.v4.f32 [%0], {%1,%2,%3,%4};"
                 :: "l"(p), "f"(v.x), "f"(v.y), "f"(v.z), "f"(v.w) : "memory");
}

// Load 128 rows x 128 dims of `src` (row-major, stride 128) TRANSPOSED into
// smem[k][r] with pitch PITCH.
__device__ __forceinline__ void load_tile_T(float* dst, const float* __restrict__ src, int rowBase) {
    for (int t = threadIdx.x; t < 128 * 32; t += 256) {
        int r  = t & 127;
        int d4 = t >> 7;
        float4 v = __ldg((const float4*)(src + (long)(rowBase + r) * DIMC) + d4);
        int d = d4 * 4;
        dst[(d + 0) * PITCH + r] = v.x;
        dst[(d + 1) * PITCH + r] = v.y;
        dst[(d + 2) * PITCH + r] = v.z;
        dst[(d + 3) * PITCH + r] = v.w;
    }
}

// Load a 128x128 weight block (already [k][c] row-major) into smem[k][c], pitch PITCH.
__device__ __forceinline__ void load_w(float* dst, const float* __restrict__ W) {
    for (int t = threadIdx.x; t < 128 * 32; t += 256) {
        int k  = t >> 5;
        int c4 = t & 31;
        float4 v = __ldg((const float4*)(W + k * DIMC) + c4);
        *(float4*)(dst + k * PITCH + c4 * 4) = v;
    }
}

// 128x128 output tile, 8x8 per thread, K=128.
__device__ __forceinline__ void sgemm_tile(const float* As, const float* Bs,
                                           float acc[8][8], int tx, int ty) {
    #pragma unroll 4
    for (int k = 0; k < 128; k++) {
        float4 a0 = *(const float4*)(As + k * PITCH + ty * 8);
        float4 a1 = *(const float4*)(As + k * PITCH + ty * 8 + 4);
        float4 b0 = *(const float4*)(Bs + k * PITCH + tx * 8);
        float4 b1 = *(const float4*)(Bs + k * PITCH + tx * 8 + 4);
        float a[8] = {a0.x, a0.y, a0.z, a0.w, a1.x, a1.y, a1.z, a1.w};
        float b[8] = {b0.x, b0.y, b0.z, b0.w, b1.x, b1.y, b1.z, b1.w};
        #pragma unroll
        for (int i = 0; i < 8; i++)
            #pragma unroll
            for (int j = 0; j < 8; j++)
                acc[i][j] += a[i] * b[j];
    }
}

// ---------------- kernels ----------------

// Normalize rows of x -> g_xn; init degree arrays to 1 (self loop).
__global__ void k_prep(const float* __restrict__ x) {
    int w    = (blockIdx.x * blockDim.x + threadIdx.x) >> 5;
    int lane = threadIdx.x & 31;
    if (w >= NUMN) return;
    float4 v = ((const float4*)(x + (long)w * DIMC))[lane];
    float ss = v.x * v.x + v.y * v.y + v.z * v.z + v.w * v.w;
    ss = warp_sum(ss);
    float s = 1.0f / fmaxf(sqrtf(ss), 1e-8f);
    float4 o = make_float4(v.x * s, v.y * s, v.z * s, v.w * s);
    ((float4*)(g_xn + (long)w * DIMC))[lane] = o;
    if (lane == 0) { g_deg1[w] = 1; g_deg2[w] = 1; }
}

__global__ void k_hist(const int* __restrict__ ei) {
    int e = blockIdx.x * blockDim.x + threadIdx.x;
    if (e < NEDGE) atomicAdd(&g_deg2[ei[NEDGE + e]], 1);
}

__global__ void k_dinv() {
    int i = blockIdx.x * blockDim.x + threadIdx.x;
    if (i < NUMN) {
        g_dinv1[i] = rsqrtf((float)g_deg1[i]);
        g_dinv2[i] = rsqrtf((float)g_deg2[i]);
    }
}

// Cosine-similarity GEMM fused with exact running top-4-smallest-sim
// (== top-4 largest distance) per row, index tiebreak like jax.lax.top_k.
__global__ __launch_bounds__(256, 1) void k_dist() {
    extern __shared__ float sm[];
    float* As = sm;                  // [128][PITCH]  rows (transposed)
    float* Bs = sm + 128 * PITCH;    // [128][PITCH]  cols (transposed), reused for S
    __shared__ float runv[128][4];
    __shared__ int   runi[128][4];

    int bid = blockIdx.x;
    int g   = bid >> 3;
    int rt  = bid & 7;
    int rowBase = g * NPG + rt * 128;
    int tid = threadIdx.x, tx = tid & 15, ty = tid >> 4;
    int warp = tid >> 5, lane = tid & 31;

    for (int t = tid; t < 128 * 4; t += 256) {
        runv[t >> 2][t & 3] = INFV;
        runi[t >> 2][t & 3] = 0x7fffffff;
    }
    load_tile_T(As, g_xn, rowBase);
    __syncthreads();

    for (int ct = 0; ct < 8; ct++) {
        load_tile_T(Bs, g_xn, g * NPG + ct * 128);
        __syncthreads();

        float acc[8][8];
        #pragma unroll
        for (int i = 0; i < 8; i++)
            #pragma unroll
            for (int j = 0; j < 8; j++) acc[i][j] = 0.0f;
        sgemm_tile(As, Bs, acc, tx, ty);
        __syncthreads();

        // dump sims into Bs (reused as S[row][col])
        #pragma unroll
        for (int i = 0; i < 8; i++) {
            *(float4*)(Bs + (ty * 8 + i) * PITCH + tx * 8)     = make_float4(acc[i][0], acc[i][1], acc[i][2], acc[i][3]);
            *(float4*)(Bs + (ty * 8 + i) * PITCH + tx * 8 + 4) = make_float4(acc[i][4], acc[i][5], acc[i][6], acc[i][7]);
        }
        __syncthreads();

        // per-row top-4 smallest sim, merged with running best
        for (int rr = 0; rr < 16; rr++) {
            int r = warp * 16 + rr;
            float v[5]; int ci[5];
            #pragma unroll
            for (int q = 0; q < 4; q++) {
                int c = lane + q * 32;
                v[q]  = Bs[r * PITCH + c];
                ci[q] = ct * 128 + c;
            }
            if (lane < 4) { v[4] = runv[r][lane]; ci[4] = runi[r][lane]; }
            else          { v[4] = INFV;          ci[4] = 0x7fffffff;   }

            #pragma unroll
            for (int p = 0; p < 4; p++) {
                float bv = v[0]; int bi = ci[0];
                #pragma unroll
                for (int q = 1; q < 5; q++)
                    if (v[q] < bv || (v[q] == bv && ci[q] < bi)) { bv = v[q]; bi = ci[q]; }
                #pragma unroll
                for (int o = 16; o; o >>= 1) {
                    float ov = __shfl_xor_sync(0xffffffffu, bv, o);
                    int   oi = __shfl_xor_sync(0xffffffffu, bi, o);
                    if (ov < bv || (ov == bv && oi < bi)) { bv = ov; bi = oi; }
                }
                #pragma unroll
                for (int q = 0; q < 5; q++)
                    if (ci[q] == bi) { v[q] = INFV; ci[q] = 0x7fffffff; }
                if (lane == p) { runv[r][p] = bv; runi[r][p] = bi; }
            }
        }
        __syncthreads();
    }

    // emit edges + degree histogram
    for (int rr = 0; rr < 16; rr++) {
        int r = warp * 16 + rr;
        if (lane < 4) {
            int node = rowBase + r;
            int dst  = g * NPG + runi[r][lane];
            g_fdst[node * 4 + lane] = dst;
            atomicAdd(&g_deg1[dst], 1);
        }
    }
}

// h = x@W (both branches), scaled by dinv[row]; writes hs and initializes acc=hs.
__global__ __launch_bounds__(256, 1) void k_gemm_h(const float* __restrict__ x,
                                                   const float* __restrict__ Wf,
                                                   const float* __restrict__ Ws) {
    extern __shared__ float sm[];
    float* As = sm;
    float* Bs = sm + 128 * PITCH;
    int rowBase = blockIdx.x * 128;
    int tid = threadIdx.x, tx = tid & 15, ty = tid >> 4;

    load_tile_T(As, x, rowBase);
    for (int m = 0; m < 2; m++) {
        __syncthreads();
        load_w(Bs, m ? Ws : Wf);
        __syncthreads();
        float acc[8][8];
        #pragma unroll
        for (int i = 0; i < 8; i++)
            #pragma unroll
            for (int j = 0; j < 8; j++) acc[i][j] = 0.0f;
        sgemm_tile(As, Bs, acc, tx, ty);

        float* hdst = m ? g_h2 : g_h1;
        float* adst = m ? g_acc2 : g_acc1;
        const float* dinv = m ? g_dinv2 : g_dinv1;
        #pragma unroll
        for (int i = 0; i < 8; i++) {
            int node = rowBase + ty * 8 + i;
            float di = __ldg(&dinv[node]);
            float4 o0 = make_float4(acc[i][0] * di, acc[i][1] * di, acc[i][2] * di, acc[i][3] * di);
            float4 o1 = make_float4(acc[i][4] * di, acc[i][5] * di, acc[i][6] * di, acc[i][7] * di);
            *(float4*)(hdst + (long)node * DIMC + tx * 8)     = o0;
            *(float4*)(hdst + (long)node * DIMC + tx * 8 + 4) = o1;
            *(float4*)(adst + (long)node * DIMC + tx * 8)     = o0;
            *(float4*)(adst + (long)node * DIMC + tx * 8 + 4) = o1;
        }
    }
}

__global__ void k_agg_feat() {
    int gw   = (blockIdx.x * blockDim.x + threadIdx.x) >> 5;
    int lane = threadIdx.x & 31;
    if (gw >= NUMN * 4) return;
    int src = gw >> 2;
    int dst = g_fdst[gw];
    float4 v = *(const float4*)(g_h1 + (long)src * DIMC + lane * 4);
    red4(g_acc1 + (long)dst * DIMC + lane * 4, v);
}

__global__ void k_agg_stru(const int* __restrict__ ei) {
    int e    = (blockIdx.x * blockDim.x + threadIdx.x) >> 5;
    int lane = threadIdx.x & 31;
    if (e >= NEDGE) return;
    int s = ei[e];
    int d = ei[NEDGE + e];
    float4 v = *(const float4*)(g_h2 + (long)s * DIMC + lane * 4);
    red4(g_acc2 + (long)d * DIMC + lane * 4, v);
}

// out = LN(relu(dinv[d]*acc[d] + b)) * gamma + beta, for both branches
__global__ void k_branch(const float* __restrict__ bf, const float* __restrict__ bs,
                         const float* __restrict__ gf, const float* __restrict__ bef,
                         const float* __restrict__ gs, const float* __restrict__ bes) {
    int w    = (blockIdx.x * blockDim.x + threadIdx.x) >> 5;
    int lane = threadIdx.x & 31;
    if (w >= 2 * NUMN) return;
    int branch = w >> 16;
    int node   = w & (NUMN - 1);

    const float* acc  = branch ? g_acc2  : g_acc1;
    float di          = branch ? g_dinv2[node] : g_dinv1[node];
    const float* bias = branch ? bs  : bf;
    const float* gam  = branch ? gs  : gf;
    const float* bet  = branch ? bes : bef;

    float4 a  = *(const float4*)(acc + (long)node * DIMC + lane * 4);
    float4 b4 = ((const float4*)bias)[lane];
    float v0 = fmaxf(di * a.x + b4.x, 0.0f);
    float v1 = fmaxf(di * a.y + b4.y, 0.0f);
    float v2 = fmaxf(di * a.z + b4.z, 0.0f);
    float v3 = fmaxf(di * a.w + b4.w, 0.0f);

    float m = warp_sum(v0 + v1 + v2 + v3) * (1.0f / 128.0f);
    float d0 = v0 - m, d1 = v1 - m, d2 = v2 - m, d3 = v3 - m;
    float var = warp_sum(d0 * d0 + d1 * d1 + d2 * d2 + d3 * d3) * (1.0f / 128.0f);
    float rs = rsqrtf(var + 1e-5f);

    float4 g4 = ((const float4*)gam)[lane];
    float4 t4 = ((const float4*)bet)[lane];
    float4 o = make_float4(d0 * rs * g4.x + t4.x, d1 * rs * g4.y + t4.y,
                           d2 * rs * g4.z + t4.z, d3 * rs * g4.w + t4.w);
    float* dst = branch ? g_stru : g_feat;
    *(float4*)(dst + (long)node * DIMC + lane * 4) = o;
}

// gate = sigmoid([feat, stru] @ W_gate + b_gate)
__global__ __launch_bounds__(256, 1) void k_gemm_gate(const float* __restrict__ Wg,
                                                      const float* __restrict__ bg) {
    extern __shared__ float sm[];
    float* As = sm;
    float* Bs = sm + 128 * PITCH;
    int rowBase = blockIdx.x * 128;
    int tid = threadIdx.x, tx = tid & 15, ty = tid >> 4;

    float acc[8][8];
    #pragma unroll
    for (int i = 0; i < 8; i++)
        #pragma unroll
        for (int j = 0; j < 8; j++) acc[i][j] = 0.0f;

    for (int kt = 0; kt < 2; kt++) {
        __syncthreads();
        load_tile_T(As, kt ? g_stru : g_feat, rowBase);
        load_w(Bs, Wg + kt * 128 * DIMC);
        __syncthreads();
        sgemm_tile(As, Bs, acc, tx, ty);
    }

    #pragma unroll
    for (int i = 0; i < 8; i++) {
        int node = rowBase + ty * 8 + i;
        float o[8];
        #pragma unroll
        for (int j = 0; j < 8; j++) {
            float val = acc[i][j] + __ldg(&bg[tx * 8 + j]);
            o[j] = 1.0f / (1.0f + __expf(-val));
        }
        *(float4*)(g_gate + (long)node * DIMC + tx * 8)     = make_float4(o[0], o[1], o[2], o[3]);
        *(float4*)(g_gate + (long)node * DIMC + tx * 8 + 4) = make_float4(o[4], o[5], o[6], o[7]);
    }
}

// fus = LN(gate*feat + (1-gate)*stru) * g_fus + be_fus + x
__global__ void k_final(const float* __restrict__ x, const float* __restrict__ gfu,
                        const float* __restrict__ befu, float* __restrict__ out) {
    int w    = (blockIdx.x * blockDim.x + threadIdx.x) >> 5;
    int lane = threadIdx.x & 31;
    if (w >= NUMN) return;
    long base = (long)w * DIMC + lane * 4;
    float4 f  = *(const float4*)(g_feat + base);
    float4 s  = *(const float4*)(g_stru + base);
    float4 gt = *(const float4*)(g_gate + base);

    float v0 = gt.x * f.x + (1.0f - gt.x) * s.x;
    float v1 = gt.y * f.y + (1.0f - gt.y) * s.y;
    float v2 = gt.z * f.z + (1.0f - gt.z) * s.z;
    float v3 = gt.w * f.w + (1.0f - gt.w) * s.w;

    float m = warp_sum(v0 + v1 + v2 + v3) * (1.0f / 128.0f);
    float d0 = v0 - m, d1 = v1 - m, d2 = v2 - m, d3 = v3 - m;
    float var = warp_sum(d0 * d0 + d1 * d1 + d2 * d2 + d3 * d3) * (1.0f / 128.0f);
    float rs = rsqrtf(var + 1e-5f);

    float4 g4 = ((const float4*)gfu)[lane];
    float4 t4 = ((const float4*)befu)[lane];
    float4 xx = *(const float4*)(x + base);
    float4 o = make_float4(d0 * rs * g4.x + t4.x + xx.x,
                           d1 * rs * g4.y + t4.y + xx.y,
                           d2 * rs * g4.z + t4.z + xx.z,
                           d3 * rs * g4.w + t4.w + xx.w);
    *(float4*)(out + base) = o;
}

// ---------------- launch ----------------
extern "C" void kernel_launch(void* const* d_in, const int* in_sizes, int n_in,
                              void* d_out, int out_size) {
    const float* x   = (const float*)d_in[0];
    const int*   ei  = (const int*)  d_in[1];
    const float* Wf  = (const float*)d_in[2];
    const float* bf  = (const float*)d_in[3];
    const float* Ws  = (const float*)d_in[4];
    const float* bs  = (const float*)d_in[5];
    const float* Wg  = (const float*)d_in[6];
    const float* bg  = (const float*)d_in[7];
    const float* gf  = (const float*)d_in[8];
    const float* bef = (const float*)d_in[9];
    const float* gs  = (const float*)d_in[10];
    const float* bes = (const float*)d_in[11];
    const float* gfu = (const float*)d_in[12];
    const float* befu= (const float*)d_in[13];
    float* out = (float*)d_out;

    cudaFuncSetAttribute(k_dist,      cudaFuncAttributeMaxDynamicSharedMemorySize, SMEM_BYTES);
    cudaFuncSetAttribute(k_gemm_h,    cudaFuncAttributeMaxDynamicSharedMemorySize, SMEM_BYTES);
    cudaFuncSetAttribute(k_gemm_gate, cudaFuncAttributeMaxDynamicSharedMemorySize, SMEM_BYTES);

    k_prep<<<8192, 256>>>(x);
    k_hist<<<8192, 256>>>(ei);
    k_dist<<<512, 256, SMEM_BYTES>>>();
    k_dinv<<<256, 256>>>();
    k_gemm_h<<<512, 256, SMEM_BYTES>>>(x, Wf, Ws);
    k_agg_feat<<<32768, 256>>>();
    k_agg_stru<<<262144, 256>>>(ei);
    k_branch<<<16384, 256>>>(bf, bs, gf, bef, gs, bes);
    k_gemm_gate<<<512, 256, SMEM_BYTES>>>(Wg, bg);
    k_final<<<8192, 256>>>(x, gfu, befu, out);
}

// round 7
// speedup vs baseline: 1.0645x; 1.0645x over previous
#include <cuda_runtime.h>
#include <math.h>

#define NUMN  65536
#define NG    64
#define NPG   1024
#define DIMC  128
#define NEDGE 2097152
#define PITCH 132
#define SMEM_BYTES  (2 * 128 * PITCH * 4)
#define SMEM_TAIL   (3 * 128 * PITCH * 4)
#define INFV  3.402823466e38f

// ---------------- scratch (device globals; no allocation allowed) ----------------
__device__ float g_xn  [NUMN * DIMC];   // normalized x
__device__ float g_h1  [NUMN * DIMC];   // dinv-scaled h_feat
__device__ float g_h2  [NUMN * DIMC];   // dinv-scaled h_stru
__device__ float g_acc1[NUMN * DIMC];   // aggregation accumulators (init = self term)
__device__ float g_acc2[NUMN * DIMC];
__device__ int   g_fdst[NUMN * 4];      // k-farthest dst indices (global node ids)
__device__ int   g_deg1[NUMN];
__device__ int   g_deg2[NUMN];
__device__ float g_dinv1[NUMN];
__device__ float g_dinv2[NUMN];

// ---------------- helpers ----------------
__device__ __forceinline__ float warp_sum(float v) {
    #pragma unroll
    for (int o = 16; o; o >>= 1) v += __shfl_xor_sync(0xffffffffu, v, o);
    return v;
}

__device__ __forceinline__ void red4(float* p, float4 v) {
    asm volatile("red.global.add.v4.f32 [%0], {%1,%2,%3,%4};"
                 :: "l"(p), "f"(v.x), "f"(v.y), "f"(v.z), "f"(v.w) : "memory");
}

// Load 128 rows x 128 dims of `src` TRANSPOSED into smem[k][r], pitch PITCH.
__device__ __forceinline__ void load_tile_T(float* dst, const float* __restrict__ src, int rowBase) {
    for (int t = threadIdx.x; t < 128 * 32; t += 256) {
        int r  = t & 127;
        int d4 = t >> 7;
        float4 v = __ldg((const float4*)(src + (long)(rowBase + r) * DIMC) + d4);
        int d = d4 * 4;
        dst[(d + 0) * PITCH + r] = v.x;
        dst[(d + 1) * PITCH + r] = v.y;
        dst[(d + 2) * PITCH + r] = v.z;
        dst[(d + 3) * PITCH + r] = v.w;
    }
}

// Load a 128x128 weight block ([k][c] row-major) into smem[k][c], pitch PITCH.
__device__ __forceinline__ void load_w(float* dst, const float* __restrict__ W) {
    for (int t = threadIdx.x; t < 128 * 32; t += 256) {
        int k  = t >> 5;
        int c4 = t & 31;
        float4 v = __ldg((const float4*)(W + k * DIMC) + c4);
        *(float4*)(dst + k * PITCH + c4 * 4) = v;
    }
}

// 128x128 output tile, 8x8 per thread, K=128.
__device__ __forceinline__ void sgemm_tile(const float* As, const float* Bs,
                                           float acc[8][8], int tx, int ty) {
    #pragma unroll 4
    for (int k = 0; k < 128; k++) {
        float4 a0 = *(const float4*)(As + k * PITCH + ty * 8);
        float4 a1 = *(const float4*)(As + k * PITCH + ty * 8 + 4);
        float4 b0 = *(const float4*)(Bs + k * PITCH + tx * 8);
        float4 b1 = *(const float4*)(Bs + k * PITCH + tx * 8 + 4);
        float a[8] = {a0.x, a0.y, a0.z, a0.w, a1.x, a1.y, a1.z, a1.w};
        float b[8] = {b0.x, b0.y, b0.z, b0.w, b1.x, b1.y, b1.z, b1.w};
        #pragma unroll
        for (int i = 0; i < 8; i++)
            #pragma unroll
            for (int j = 0; j < 8; j++)
                acc[i][j] += a[i] * b[j];
    }
}

// ---------------- kernels ----------------

__global__ void k_prep(const float* __restrict__ x) {
    int w    = (blockIdx.x * blockDim.x + threadIdx.x) >> 5;
    int lane = threadIdx.x & 31;
    if (w >= NUMN) return;
    float4 v = ((const float4*)(x + (long)w * DIMC))[lane];
    float ss = v.x * v.x + v.y * v.y + v.z * v.z + v.w * v.w;
    ss = warp_sum(ss);
    float s = 1.0f / fmaxf(sqrtf(ss), 1e-8f);
    float4 o = make_float4(v.x * s, v.y * s, v.z * s, v.w * s);
    ((float4*)(g_xn + (long)w * DIMC))[lane] = o;
    if (lane == 0) { g_deg1[w] = 1; g_deg2[w] = 1; }
}

__global__ void k_hist(const int* __restrict__ ei) {
    int e = blockIdx.x * blockDim.x + threadIdx.x;
    if (e < NEDGE) atomicAdd(&g_deg2[ei[NEDGE + e]], 1);
}

__global__ void k_dinv() {
    int i = blockIdx.x * blockDim.x + threadIdx.x;
    if (i < NUMN) {
        g_dinv1[i] = rsqrtf((float)g_deg1[i]);
        g_dinv2[i] = rsqrtf((float)g_deg2[i]);
    }
}

// Cosine-similarity GEMM fused with exact running top-4-smallest-sim per row.
__global__ __launch_bounds__(256, 1) void k_dist() {
    extern __shared__ float sm[];
    float* As = sm;                  // [128][PITCH]  rows (transposed)
    float* Bs = sm + 128 * PITCH;    // [128][PITCH]  cols (transposed), reused for S
    __shared__ float runv[128][4];
    __shared__ int   runi[128][4];

    int bid = blockIdx.x;
    int g   = bid >> 3;
    int rt  = bid & 7;
    int rowBase = g * NPG + rt * 128;
    int tid = threadIdx.x, tx = tid & 15, ty = tid >> 4;
    int warp = tid >> 5, lane = tid & 31;

    for (int t = tid; t < 128 * 4; t += 256) {
        runv[t >> 2][t & 3] = INFV;
        runi[t >> 2][t & 3] = 0x7fffffff;
    }
    load_tile_T(As, g_xn, rowBase);
    __syncthreads();

    for (int ct = 0; ct < 8; ct++) {
        load_tile_T(Bs, g_xn, g * NPG + ct * 128);
        __syncthreads();

        float acc[8][8];
        #pragma unroll
        for (int i = 0; i < 8; i++)
            #pragma unroll
            for (int j = 0; j < 8; j++) acc[i][j] = 0.0f;
        sgemm_tile(As, Bs, acc, tx, ty);
        __syncthreads();

        // dump sims into Bs (reused as S[row][col])
        #pragma unroll
        for (int i = 0; i < 8; i++) {
            *(float4*)(Bs + (ty * 8 + i) * PITCH + tx * 8)     = make_float4(acc[i][0], acc[i][1], acc[i][2], acc[i][3]);
            *(float4*)(Bs + (ty * 8 + i) * PITCH + tx * 8 + 4) = make_float4(acc[i][4], acc[i][5], acc[i][6], acc[i][7]);
        }
        __syncthreads();

        // per-row top-4 smallest sim, merged with running best
        for (int rr = 0; rr < 16; rr++) {
            int r = warp * 16 + rr;
            float v[5]; int ci[5];
            #pragma unroll
            for (int q = 0; q < 4; q++) {
                int c = lane + q * 32;
                v[q]  = Bs[r * PITCH + c];
                ci[q] = ct * 128 + c;
            }

            // Fast rejection: all candidate indices exceed stored ones, so a
            // candidate only enters on STRICT v < current 4th-smallest.
            float thr = runv[r][3];
            bool cand = (v[0] < thr) | (v[1] < thr) | (v[2] < thr) | (v[3] < thr);
            if (!__any_sync(0xffffffffu, cand)) continue;

            if (lane < 4) { v[4] = runv[r][lane]; ci[4] = runi[r][lane]; }
            else          { v[4] = INFV;          ci[4] = 0x7fffffff;   }

            #pragma unroll
            for (int p = 0; p < 4; p++) {
                float bv = v[0]; int bi = ci[0];
                #pragma unroll
                for (int q = 1; q < 5; q++)
                    if (v[q] < bv || (v[q] == bv && ci[q] < bi)) { bv = v[q]; bi = ci[q]; }
                #pragma unroll
                for (int o = 16; o; o >>= 1) {
                    float ov = __shfl_xor_sync(0xffffffffu, bv, o);
                    int   oi = __shfl_xor_sync(0xffffffffu, bi, o);
                    if (ov < bv || (ov == bv && oi < bi)) { bv = ov; bi = oi; }
                }
                #pragma unroll
                for (int q = 0; q < 5; q++)
                    if (ci[q] == bi) { v[q] = INFV; ci[q] = 0x7fffffff; }
                if (lane == p) { runv[r][p] = bv; runi[r][p] = bi; }
            }
        }
        __syncthreads();
    }

    // emit edges + degree histogram
    for (int rr = 0; rr < 16; rr++) {
        int r = warp * 16 + rr;
        if (lane < 4) {
            int node = rowBase + r;
            int dst  = g * NPG + runi[r][lane];
            g_fdst[node * 4 + lane] = dst;
            atomicAdd(&g_deg1[dst], 1);
        }
    }
}

// h = x@W (both branches), scaled by dinv[row]; writes hs and initializes acc=hs.
__global__ __launch_bounds__(256, 1) void k_gemm_h(const float* __restrict__ x,
                                                   const float* __restrict__ Wf,
                                                   const float* __restrict__ Ws) {
    extern __shared__ float sm[];
    float* As = sm;
    float* Bs = sm + 128 * PITCH;
    int rowBase = blockIdx.x * 128;
    int tid = threadIdx.x, tx = tid & 15, ty = tid >> 4;

    load_tile_T(As, x, rowBase);
    for (int m = 0; m < 2; m++) {
        __syncthreads();
        load_w(Bs, m ? Ws : Wf);
        __syncthreads();
        float acc[8][8];
        #pragma unroll
        for (int i = 0; i < 8; i++)
            #pragma unroll
            for (int j = 0; j < 8; j++) acc[i][j] = 0.0f;
        sgemm_tile(As, Bs, acc, tx, ty);

        float* hdst = m ? g_h2 : g_h1;
        float* adst = m ? g_acc2 : g_acc1;
        const float* dinv = m ? g_dinv2 : g_dinv1;
        #pragma unroll
        for (int i = 0; i < 8; i++) {
            int node = rowBase + ty * 8 + i;
            float di = __ldg(&dinv[node]);
            float4 o0 = make_float4(acc[i][0] * di, acc[i][1] * di, acc[i][2] * di, acc[i][3] * di);
            float4 o1 = make_float4(acc[i][4] * di, acc[i][5] * di, acc[i][6] * di, acc[i][7] * di);
            *(float4*)(hdst + (long)node * DIMC + tx * 8)     = o0;
            *(float4*)(hdst + (long)node * DIMC + tx * 8 + 4) = o1;
            *(float4*)(adst + (long)node * DIMC + tx * 8)     = o0;
            *(float4*)(adst + (long)node * DIMC + tx * 8 + 4) = o1;
        }
    }
}

__global__ void k_agg_feat() {
    int gw   = (blockIdx.x * blockDim.x + threadIdx.x) >> 5;
    int lane = threadIdx.x & 31;
    if (gw >= NUMN * 4) return;
    int src = gw >> 2;
    int dst = g_fdst[gw];
    float4 v = *(const float4*)(g_h1 + (long)src * DIMC + lane * 4);
    red4(g_acc1 + (long)dst * DIMC + lane * 4, v);
}

__global__ void k_agg_stru(const int* __restrict__ ei) {
    int e    = (blockIdx.x * blockDim.x + threadIdx.x) >> 5;
    int lane = threadIdx.x & 31;
    if (e >= NEDGE) return;
    int s = ei[e];
    int d = ei[NEDGE + e];
    float4 v = *(const float4*)(g_h2 + (long)s * DIMC + lane * 4);
    red4(g_acc2 + (long)d * DIMC + lane * 4, v);
}

// Fused tail: branch LNs -> gate GEMM (K=256) -> sigmoid -> gated fusion -> LN -> residual.
// smem planes: Fs = feat^T [k][r], Ss = stru^T [k][r], Ws = weights / later gate (row-major).
__global__ __launch_bounds__(256, 1) void k_tail(
    const float* __restrict__ x,
    const float* __restrict__ bf, const float* __restrict__ bs,
    const float* __restrict__ gf, const float* __restrict__ bef,
    const float* __restrict__ gs, const float* __restrict__ bes,
    const float* __restrict__ Wg, const float* __restrict__ bg,
    const float* __restrict__ gfu, const float* __restrict__ befu,
    float* __restrict__ out)
{
    extern __shared__ float sm[];
    float* Fs = sm;
    float* Ss = sm + 128 * PITCH;
    float* Ws = sm + 2 * 128 * PITCH;

    int rowBase = blockIdx.x * 128;
    int tid = threadIdx.x, tx = tid & 15, ty = tid >> 4;
    int warp = tid >> 5, lane = tid & 31;

    // ---- step 1: branch LNs, written transposed into Fs/Ss ----
    for (int grp = 0; grp < 4; grp++) {
        int r0 = warp * 16 + grp * 4;
        float U1[4][4], U2[4][4];
        float sum1[4] = {0,0,0,0}, ss1[4] = {0,0,0,0};
        float sum2[4] = {0,0,0,0}, ss2[4] = {0,0,0,0};
        float di1[4], di2[4];
        #pragma unroll
        for (int m = 0; m < 4; m++) {
            int node = rowBase + r0 + m;
            di1[m] = __ldg(&g_dinv1[node]);
            di2[m] = __ldg(&g_dinv2[node]);
        }
        #pragma unroll
        for (int q = 0; q < 4; q++) {
            int k = q * 32 + lane;
            float bfv = __ldg(&bf[k]);
            float bsv = __ldg(&bs[k]);
            #pragma unroll
            for (int m = 0; m < 4; m++) {
                long base = (long)(rowBase + r0 + m) * DIMC + k;
                float u1 = fmaxf(di1[m] * __ldg(&g_acc1[base]) + bfv, 0.0f);
                float u2 = fmaxf(di2[m] * __ldg(&g_acc2[base]) + bsv, 0.0f);
                U1[q][m] = u1; U2[q][m] = u2;
                sum1[m] += u1; ss1[m] += u1 * u1;
                sum2[m] += u2; ss2[m] += u2 * u2;
            }
        }
        float mean1[4], rs1[4], mean2[4], rs2[4];
        #pragma unroll
        for (int m = 0; m < 4; m++) {
            float s1 = warp_sum(sum1[m]) * (1.0f / 128.0f);
            float q1 = warp_sum(ss1[m])  * (1.0f / 128.0f);
            mean1[m] = s1; rs1[m] = rsqrtf(fmaxf(q1 - s1 * s1, 0.0f) + 1e-5f);
            float s2 = warp_sum(sum2[m]) * (1.0f / 128.0f);
            float q2 = warp_sum(ss2[m])  * (1.0f / 128.0f);
            mean2[m] = s2; rs2[m] = rsqrtf(fmaxf(q2 - s2 * s2, 0.0f) + 1e-5f);
        }
        #pragma unroll
        for (int q = 0; q < 4; q++) {
            int k = q * 32 + lane;
            float g1 = __ldg(&gf[k]),  e1 = __ldg(&bef[k]);
            float g2 = __ldg(&gs[k]),  e2 = __ldg(&bes[k]);
            float4 o1, o2;
            o1.x = (U1[q][0] - mean1[0]) * rs1[0] * g1 + e1;
            o1.y = (U1[q][1] - mean1[1]) * rs1[1] * g1 + e1;
            o1.z = (U1[q][2] - mean1[2]) * rs1[2] * g1 + e1;
            o1.w = (U1[q][3] - mean1[3]) * rs1[3] * g1 + e1;
            o2.x = (U2[q][0] - mean2[0]) * rs2[0] * g2 + e2;
            o2.y = (U2[q][1] - mean2[1]) * rs2[1] * g2 + e2;
            o2.z = (U2[q][2] - mean2[2]) * rs2[2] * g2 + e2;
            o2.w = (U2[q][3] - mean2[3]) * rs2[3] * g2 + e2;
            *(float4*)(Fs + k * PITCH + r0) = o1;   // rows r0..r0+3 at dim k
            *(float4*)(Ss + k * PITCH + r0) = o2;
        }
    }
    __syncthreads();

    // ---- step 2: gate GEMM, K=256 (feat half then stru half) ----
    float acc[8][8];
    #pragma unroll
    for (int i = 0; i < 8; i++)
        #pragma unroll
        for (int j = 0; j < 8; j++) acc[i][j] = 0.0f;

    load_w(Ws, Wg);
    __syncthreads();
    sgemm_tile(Fs, Ws, acc, tx, ty);
    __syncthreads();
    load_w(Ws, Wg + 128 * DIMC);
    __syncthreads();
    sgemm_tile(Ss, Ws, acc, tx, ty);
    __syncthreads();

    // ---- step 3: sigmoid + dump gate row-major into Ws ----
    #pragma unroll
    for (int i = 0; i < 8; i++) {
        int row = ty * 8 + i;
        float o[8];
        #pragma unroll
        for (int j = 0; j < 8; j++) {
            float val = acc[i][j] + __ldg(&bg[tx * 8 + j]);
            o[j] = 1.0f / (1.0f + __expf(-val));
        }
        *(float4*)(Ws + row * PITCH + tx * 8)     = make_float4(o[0], o[1], o[2], o[3]);
        *(float4*)(Ws + row * PITCH + tx * 8 + 4) = make_float4(o[4], o[5], o[6], o[7]);
    }
    __syncthreads();

    // ---- step 4: gated fusion + LN + residual, 4 rows per warp group ----
    for (int grp = 0; grp < 4; grp++) {
        int r0 = warp * 16 + grp * 4;
        float U[4][4];
        float sum[4] = {0,0,0,0}, ssq[4] = {0,0,0,0};
        #pragma unroll
        for (int q = 0; q < 4; q++) {
            int k = q * 32 + lane;
            float4 f4 = *(const float4*)(Fs + k * PITCH + r0);
            float4 s4 = *(const float4*)(Ss + k * PITCH + r0);
            const float* fp = (const float*)&f4;
            const float* sp = (const float*)&s4;
            #pragma unroll
            for (int m = 0; m < 4; m++) {
                float g = Ws[(r0 + m) * PITCH + k];
                float u = sp[m] + g * (fp[m] - sp[m]);
                U[q][m] = u;
                sum[m] += u; ssq[m] += u * u;
            }
        }
        float mean[4], rs[4];
        #pragma unroll
        for (int m = 0; m < 4; m++) {
            float s = warp_sum(sum[m]) * (1.0f / 128.0f);
            float q2 = warp_sum(ssq[m]) * (1.0f / 128.0f);
            mean[m] = s; rs[m] = rsqrtf(fmaxf(q2 - s * s, 0.0f) + 1e-5f);
        }
        #pragma unroll
        for (int q = 0; q < 4; q++) {
            int k = q * 32 + lane;
            float gk = __ldg(&gfu[k]);
            float ek = __ldg(&befu[k]);
            #pragma unroll
            for (int m = 0; m < 4; m++) {
                long base = (long)(rowBase + r0 + m) * DIMC + k;
                out[base] = (U[q][m] - mean[m]) * rs[m] * gk + ek + __ldg(&x[base]);
            }
        }
    }
}

// ---------------- launch ----------------
extern "C" void kernel_launch(void* const* d_in, const int* in_sizes, int n_in,
                              void* d_out, int out_size) {
    const float* x   = (const float*)d_in[0];
    const int*   ei  = (const int*)  d_in[1];
    const float* Wf  = (const float*)d_in[2];
    const float* bf  = (const float*)d_in[3];
    const float* Ws  = (const float*)d_in[4];
    const float* bs  = (const float*)d_in[5];
    const float* Wg  = (const float*)d_in[6];
    const float* bg  = (const float*)d_in[7];
    const float* gf  = (const float*)d_in[8];
    const float* bef = (const float*)d_in[9];
    const float* gs  = (const float*)d_in[10];
    const float* bes = (const float*)d_in[11];
    const float* gfu = (const float*)d_in[12];
    const float* befu= (const float*)d_in[13];
    float* out = (float*)d_out;

    cudaFuncSetAttribute(k_dist,   cudaFuncAttributeMaxDynamicSharedMemorySize, SMEM_BYTES);
    cudaFuncSetAttribute(k_gemm_h, cudaFuncAttributeMaxDynamicSharedMemorySize, SMEM_BYTES);
    cudaFuncSetAttribute(k_tail,   cudaFuncAttributeMaxDynamicSharedMemorySize, SMEM_TAIL);

    k_prep<<<8192, 256>>>(x);
    k_hist<<<8192, 256>>>(ei);
    k_dist<<<512, 256, SMEM_BYTES>>>();
    k_dinv<<<256, 256>>>();
    k_gemm_h<<<512, 256, SMEM_BYTES>>>(x, Wf, Ws);
    k_agg_feat<<<32768, 256>>>();
    k_agg_stru<<<262144, 256>>>(ei);
    k_tail<<<512, 256, SMEM_TAIL>>>(x, bf, bs, gf, bef, gs, bes, Wg, bg, gfu, befu, out);
}